// round 3
// baseline (speedup 1.0000x reference)
#include <cuda_runtime.h>
#include <cuda_bf16.h>
#include <cstddef>

// Problem constants (fixed by the dataset)
#define N_NODES 100000
#define N_EDGES 1600000
#define D       128
#define ND      ((size_t)N_NODES * D)   // 12.8M floats

// ---------------------------------------------------------------------------
// Scratch: __device__ globals (no allocation allowed anywhere).
//   g_deg : degree, then overwritten with 1/max(deg,1)
//   g_agg : SpMM accumulator (51.2 MB)  -- L2-resident
//   g_z1  : layer-1 output (51.2 MB)
// ---------------------------------------------------------------------------
__device__ __align__(16) float g_deg[N_NODES];
__device__ __align__(16) float g_agg[ND];
__device__ __align__(16) float g_z1[ND];

// ---------------------------------------------------------------------------
// Zero a float buffer with float4 stores
// ---------------------------------------------------------------------------
__global__ void zero_f4_kernel(float4* __restrict__ p, int n4) {
    int i = blockIdx.x * blockDim.x + threadIdx.x;
    if (i < n4) p[i] = make_float4(0.f, 0.f, 0.f, 0.f);
}

// ---------------------------------------------------------------------------
// Out-degree histogram (float counts, atomic)
// ---------------------------------------------------------------------------
__global__ void degree_kernel(const int* __restrict__ src, float* __restrict__ deg) {
    int e = blockIdx.x * blockDim.x + threadIdx.x;
    if (e < N_EDGES) atomicAdd(&deg[src[e]], 1.0f);
}

// deg[i] <- 1 / max(deg[i], 1)
__global__ void inv_kernel(float* __restrict__ deg) {
    int i = blockIdx.x * blockDim.x + threadIdx.x;
    if (i < N_NODES) deg[i] = 1.0f / fmaxf(deg[i], 1.0f);
}

// ---------------------------------------------------------------------------
// SpMM scatter: agg[dst] += h[src] * inv[src]
// One warp per edge; lane l owns floats [4l..4l+3] of the 128-float row.
// Uses sm_90+ vector float4 atomicAdd -> 4x fewer RED ops at L2.
// ---------------------------------------------------------------------------
__global__ __launch_bounds__(256)
void spmm_scatter_kernel(const float* __restrict__ h,
                         const int*   __restrict__ src,
                         const int*   __restrict__ dst,
                         const float* __restrict__ inv,
                         float*       __restrict__ agg) {
    int gwarp = (blockIdx.x * blockDim.x + threadIdx.x) >> 5;
    int lane  = threadIdx.x & 31;
    if (gwarp >= N_EDGES) return;

    int   s  = __ldg(&src[gwarp]);
    int   d  = __ldg(&dst[gwarp]);
    float sc = __ldg(&inv[s]);

    const float4* hrow = reinterpret_cast<const float4*>(h + (size_t)s * D);
    float4 v = __ldg(&hrow[lane]);
    v.x *= sc; v.y *= sc; v.z *= sc; v.w *= sc;

    float4* arow = reinterpret_cast<float4*>(agg + (size_t)d * D);
#if __CUDA_ARCH__ >= 900
    atomicAdd(&arow[lane], v);
#else
    float* a = reinterpret_cast<float*>(&arow[lane]);
    atomicAdd(a + 0, v.x); atomicAdd(a + 1, v.y);
    atomicAdd(a + 2, v.z); atomicAdd(a + 3, v.w);
#endif
}

// ---------------------------------------------------------------------------
// Dense: out[r] = prelu(agg[r] @ W + b)
// Block = 128 threads (thread t = output column t), 32 rows per block.
// A tile in smem; W read strided-coalesced (64 KB, L1/L2 resident after warmup).
// k unrolled x4 with float4 smem broadcasts.
// ---------------------------------------------------------------------------
#define GEMM_ROWS 32

__global__ __launch_bounds__(128)
void gemm_prelu_kernel(const float* __restrict__ A,
                       const float* __restrict__ W,
                       const float* __restrict__ b,
                       const float* __restrict__ prelu_a,
                       float*       __restrict__ out,
                       int nrows) {
    __shared__ float sA[GEMM_ROWS][D];

    const int r0  = blockIdx.x * GEMM_ROWS;
    const int tid = threadIdx.x;  // 0..127 = output column

    // Cooperative tile load (coalesced: consecutive tids -> consecutive addrs)
    #pragma unroll
    for (int i = 0; i < GEMM_ROWS; i++) {
        int idx = i * D + tid;            // row i, col tid
        int gr  = r0 + i;
        sA[i][tid] = (gr < nrows) ? A[(size_t)gr * D + tid] : 0.f;
    }
    __syncthreads();

    float acc[GEMM_ROWS];
    #pragma unroll
    for (int r = 0; r < GEMM_ROWS; r++) acc[r] = 0.f;

    #pragma unroll 4
    for (int k = 0; k < D; k += 4) {
        float w0 = W[(k + 0) * D + tid];
        float w1 = W[(k + 1) * D + tid];
        float w2 = W[(k + 2) * D + tid];
        float w3 = W[(k + 3) * D + tid];
        #pragma unroll
        for (int r = 0; r < GEMM_ROWS; r++) {
            float4 av = *reinterpret_cast<const float4*>(&sA[r][k]);  // broadcast LDS.128
            acc[r] = fmaf(av.x, w0, acc[r]);
            acc[r] = fmaf(av.y, w1, acc[r]);
            acc[r] = fmaf(av.z, w2, acc[r]);
            acc[r] = fmaf(av.w, w3, acc[r]);
        }
    }

    const float bb = b[tid];
    const float pa = *prelu_a;
    #pragma unroll
    for (int r = 0; r < GEMM_ROWS; r++) {
        int gr = r0 + r;
        if (gr < nrows) {
            float z = acc[r] + bb;
            out[(size_t)gr * D + tid] = (z >= 0.f) ? z : pa * z;
        }
    }
}

// ---------------------------------------------------------------------------
// Launch: deg -> inv -> [zero agg -> spmm -> gemm] x2
// All on default stream, graph-capturable, idempotent across replays.
// ---------------------------------------------------------------------------
extern "C" void kernel_launch(void* const* d_in, const int* in_sizes, int n_in,
                              void* d_out, int out_size) {
    const float* x   = (const float*)d_in[0];
    const int*   src = (const int*)  d_in[1];
    const int*   dst = (const int*)  d_in[2];
    const float* W1  = (const float*)d_in[3];
    const float* b1  = (const float*)d_in[4];
    const float* W2  = (const float*)d_in[5];
    const float* b2  = (const float*)d_in[6];
    const float* pa  = (const float*)d_in[7];
    float*       out = (float*)d_out;

    float *deg_p, *agg_p, *z1_p;
    cudaGetSymbolAddress((void**)&deg_p, g_deg);
    cudaGetSymbolAddress((void**)&agg_p, g_agg);
    cudaGetSymbolAddress((void**)&z1_p,  g_z1);

    const int TB = 256;

    // degree + inverse
    {
        int n4 = N_NODES / 4;  // 100000 % 4 == 0
        zero_f4_kernel<<<(n4 + TB - 1) / TB, TB>>>((float4*)deg_p, n4);
        degree_kernel<<<(N_EDGES + TB - 1) / TB, TB>>>(src, deg_p);
        inv_kernel<<<(N_NODES + TB - 1) / TB, TB>>>(deg_p);
    }

    const int n4_agg     = (int)(ND / 4);                       // 3.2M float4
    const int zero_grid  = (n4_agg + TB - 1) / TB;
    const int spmm_grid  = (N_EDGES * 32 + TB - 1) / TB;        // warp per edge
    const int gemm_grid  = (N_NODES + GEMM_ROWS - 1) / GEMM_ROWS;

    // Layer 1: x -> z1
    zero_f4_kernel<<<zero_grid, TB>>>((float4*)agg_p, n4_agg);
    spmm_scatter_kernel<<<spmm_grid, TB>>>(x, src, dst, deg_p, agg_p);
    gemm_prelu_kernel<<<gemm_grid, 128>>>(agg_p, W1, b1, pa, z1_p, N_NODES);

    // Layer 2: z1 -> out
    zero_f4_kernel<<<zero_grid, TB>>>((float4*)agg_p, n4_agg);
    spmm_scatter_kernel<<<spmm_grid, TB>>>(z1_p, src, dst, deg_p, agg_p);
    gemm_prelu_kernel<<<gemm_grid, 128>>>(agg_p, W2, b2, pa, out, N_NODES);
}

// round 4
// speedup vs baseline: 1.5538x; 1.5538x over previous
#include <cuda_runtime.h>
#include <cuda_bf16.h>
#include <cstddef>

// Problem constants (fixed by the dataset)
#define N_NODES 100000
#define N_EDGES 1600000
#define D       128
#define ND      ((size_t)N_NODES * D)   // 12.8M floats

#define SCAN_B   1024
#define N_SCANBLK ((N_NODES + SCAN_B - 1) / SCAN_B)   // 98

// ---------------------------------------------------------------------------
// Scratch (__device__ globals; no allocation allowed anywhere)
// ---------------------------------------------------------------------------
__device__ __align__(16) float g_deg[N_NODES];        // out-degree -> 1/max(deg,1)
__device__ __align__(16) int   g_counts[N_NODES];     // in-degree histogram (by dst)
__device__ __align__(16) int   g_cursor[N_NODES];     // CSR fill cursors
__device__ __align__(16) int   g_rowptr[N_NODES + 1]; // CSR row pointers (by dst)
__device__ __align__(16) int   g_bsums[N_SCANBLK];    // scan partials
__device__ __align__(16) int   g_eidx[N_EDGES];       // CSR column indices (src node)
__device__ __align__(16) float g_xs[ND];              // prescaled layer-1 input (x * inv)
__device__ __align__(16) float g_agg[ND];             // SpMM result
__device__ __align__(16) float g_z1[ND];              // layer-1 output (prescaled by inv)

// ---------------------------------------------------------------------------
// f32x2 packed-FMA helpers (sm_103a FFMA2 — only reachable via PTX)
// ---------------------------------------------------------------------------
__device__ __forceinline__ unsigned long long pack2(float lo, float hi) {
    unsigned long long r;
    asm("mov.b64 %0, {%1, %2};" : "=l"(r) : "f"(lo), "f"(hi));
    return r;
}
__device__ __forceinline__ void fma2(unsigned long long& d,
                                     unsigned long long a, unsigned long long b) {
    asm("fma.rn.f32x2 %0, %1, %2, %0;" : "+l"(d) : "l"(a), "l"(b));
}
__device__ __forceinline__ float2 unpack2(unsigned long long v) {
    float lo, hi;
    asm("mov.b64 {%0, %1}, %2;" : "=f"(lo), "=f"(hi) : "l"(v));
    return make_float2(lo, hi);
}

// ---------------------------------------------------------------------------
// Zero the small per-node buffers (deg, counts, cursor)
// ---------------------------------------------------------------------------
__global__ void zero_small_kernel(float* __restrict__ deg,
                                  int* __restrict__ counts,
                                  int* __restrict__ cursor) {
    int i = blockIdx.x * blockDim.x + threadIdx.x;
    if (i < N_NODES) { deg[i] = 0.f; counts[i] = 0; cursor[i] = 0; }
}

// Combined histograms: out-degree (by src, float) + in-degree (by dst, int)
__global__ void hist_kernel(const int* __restrict__ src, const int* __restrict__ dst,
                            float* __restrict__ deg, int* __restrict__ counts) {
    int e = blockIdx.x * blockDim.x + threadIdx.x;
    if (e < N_EDGES) {
        atomicAdd(&deg[src[e]], 1.0f);
        atomicAdd(&counts[dst[e]], 1);
    }
}

// deg[i] <- 1 / max(deg[i], 1)
__global__ void inv_kernel(float* __restrict__ deg) {
    int i = blockIdx.x * blockDim.x + threadIdx.x;
    if (i < N_NODES) deg[i] = 1.0f / fmaxf(deg[i], 1.0f);
}

// ---------------------------------------------------------------------------
// Exclusive scan of counts -> rowptr (3-kernel hierarchical scan)
// ---------------------------------------------------------------------------
__global__ __launch_bounds__(SCAN_B)
void scan_block_kernel(const int* __restrict__ counts, int* __restrict__ rowptr,
                       int* __restrict__ bsums) {
    __shared__ int s[SCAN_B];
    int i = blockIdx.x * SCAN_B + threadIdx.x;
    int v = (i < N_NODES) ? counts[i] : 0;
    s[threadIdx.x] = v;
    __syncthreads();
    #pragma unroll
    for (int off = 1; off < SCAN_B; off <<= 1) {
        int t = (threadIdx.x >= off) ? s[threadIdx.x - off] : 0;
        __syncthreads();
        s[threadIdx.x] += t;
        __syncthreads();
    }
    if (i < N_NODES) rowptr[i + 1] = s[threadIdx.x];   // inclusive -> rowptr[i+1]
    if (threadIdx.x == SCAN_B - 1) bsums[blockIdx.x] = s[SCAN_B - 1];
}

__global__ __launch_bounds__(128)
void scan_sums_kernel(int* __restrict__ bsums) {
    __shared__ int s[128];
    int v = (threadIdx.x < N_SCANBLK) ? bsums[threadIdx.x] : 0;
    s[threadIdx.x] = v;
    __syncthreads();
    #pragma unroll
    for (int off = 1; off < 128; off <<= 1) {
        int t = (threadIdx.x >= off) ? s[threadIdx.x - off] : 0;
        __syncthreads();
        s[threadIdx.x] += t;
        __syncthreads();
    }
    if (threadIdx.x < N_SCANBLK)
        bsums[threadIdx.x] = (threadIdx.x > 0) ? s[threadIdx.x - 1] : 0;  // exclusive
}

__global__ __launch_bounds__(SCAN_B)
void scan_add_kernel(int* __restrict__ rowptr, const int* __restrict__ bsums) {
    int i = blockIdx.x * SCAN_B + threadIdx.x;
    if (i < N_NODES) rowptr[i + 1] += bsums[blockIdx.x];
    if (i == 0) rowptr[0] = 0;
}

// Scatter edges into CSR order (by dst); store src index
__global__ void csr_fill_kernel(const int* __restrict__ src, const int* __restrict__ dst,
                                const int* __restrict__ rowptr, int* __restrict__ cursor,
                                int* __restrict__ eidx) {
    int e = blockIdx.x * blockDim.x + threadIdx.x;
    if (e < N_EDGES) {
        int d = dst[e];
        int pos = rowptr[d] + atomicAdd(&cursor[d], 1);
        eidx[pos] = src[e];
    }
}

// ---------------------------------------------------------------------------
// Prescale: xs[row] = x[row] * inv[row]   (float4-vectorized)
// ---------------------------------------------------------------------------
__global__ void prescale_kernel(const float4* __restrict__ x4,
                                const float* __restrict__ inv,
                                float4* __restrict__ xs4) {
    int i = blockIdx.x * blockDim.x + threadIdx.x;
    if (i < (int)(ND / 4)) {
        int row = i >> 5;                 // 32 float4 per row
        float s = inv[row];
        float4 v = x4[i];
        v.x *= s; v.y *= s; v.z *= s; v.w *= s;
        xs4[i] = v;
    }
}

// ---------------------------------------------------------------------------
// CSR gather SpMM: agg[d] = sum_{e in row d} h[eidx[e]]
// One warp per dst node; lane owns one float4 of the 128-float row.
// Inputs are already prescaled by 1/outdeg, so the loop is a bare accumulate.
// ---------------------------------------------------------------------------
__global__ __launch_bounds__(256)
void gather_kernel(const float* __restrict__ h,
                   const int* __restrict__ rowptr,
                   const int* __restrict__ eidx,
                   float* __restrict__ agg) {
    int warp = (blockIdx.x * blockDim.x + threadIdx.x) >> 5;
    int lane = threadIdx.x & 31;
    if (warp >= N_NODES) return;

    int beg = rowptr[warp];
    int end = rowptr[warp + 1];
    const float4* h4 = reinterpret_cast<const float4*>(h);
    float4 acc = make_float4(0.f, 0.f, 0.f, 0.f);

    for (int e = beg; e < end; e += 32) {
        int cnt = min(32, end - e);
        int s = (lane < cnt) ? __ldg(&eidx[e + lane]) : 0;
        int j = 0;
        for (; j + 4 <= cnt; j += 4) {                 // 4-wide MLP
            int s0 = __shfl_sync(0xFFFFFFFFu, s, j + 0);
            int s1 = __shfl_sync(0xFFFFFFFFu, s, j + 1);
            int s2 = __shfl_sync(0xFFFFFFFFu, s, j + 2);
            int s3 = __shfl_sync(0xFFFFFFFFu, s, j + 3);
            float4 v0 = __ldg(&h4[(size_t)s0 * 32 + lane]);
            float4 v1 = __ldg(&h4[(size_t)s1 * 32 + lane]);
            float4 v2 = __ldg(&h4[(size_t)s2 * 32 + lane]);
            float4 v3 = __ldg(&h4[(size_t)s3 * 32 + lane]);
            acc.x += v0.x + v1.x + v2.x + v3.x;
            acc.y += v0.y + v1.y + v2.y + v3.y;
            acc.z += v0.z + v1.z + v2.z + v3.z;
            acc.w += v0.w + v1.w + v2.w + v3.w;
        }
        for (; j < cnt; j++) {
            int ss = __shfl_sync(0xFFFFFFFFu, s, j);
            float4 v = __ldg(&h4[(size_t)ss * 32 + lane]);
            acc.x += v.x; acc.y += v.y; acc.z += v.z; acc.w += v.w;
        }
    }
    reinterpret_cast<float4*>(agg)[(size_t)warp * 32 + lane] = acc;
}

// ---------------------------------------------------------------------------
// Dense: out[r] = prelu(agg[r] @ W + b) [* rowscale[r] if given]
// 128 threads (thread = output col), 32 rows/block, FFMA2 over k-pairs:
// acc2[r] packs (even-k partial, odd-k partial); horizontal add at the end.
// A operand comes out of smem as ulonglong2 (LDS.128, zero pack movs).
// ---------------------------------------------------------------------------
#define GEMM_ROWS 32

__global__ __launch_bounds__(128)
void gemm_prelu_kernel(const float* __restrict__ A,
                       const float* __restrict__ W,
                       const float* __restrict__ b,
                       const float* __restrict__ prelu_a,
                       const float* __restrict__ rowscale,   // may be nullptr
                       float*       __restrict__ out,
                       int nrows) {
    __shared__ __align__(16) float sA[GEMM_ROWS][D];

    const int r0  = blockIdx.x * GEMM_ROWS;
    const int tid = threadIdx.x;  // output column

    #pragma unroll
    for (int i = 0; i < GEMM_ROWS; i++) {
        int gr = r0 + i;
        sA[i][tid] = (gr < nrows) ? A[(size_t)gr * D + tid] : 0.f;
    }
    __syncthreads();

    unsigned long long acc2[GEMM_ROWS];
    #pragma unroll
    for (int r = 0; r < GEMM_ROWS; r++) acc2[r] = pack2(0.f, 0.f);

    #pragma unroll 4
    for (int k = 0; k < D; k += 4) {
        float w0 = W[(k + 0) * D + tid];
        float w1 = W[(k + 1) * D + tid];
        float w2 = W[(k + 2) * D + tid];
        float w3 = W[(k + 3) * D + tid];
        unsigned long long wA = pack2(w0, w1);
        unsigned long long wB = pack2(w2, w3);
        #pragma unroll
        for (int r = 0; r < GEMM_ROWS; r++) {
            ulonglong2 a2 = *reinterpret_cast<const ulonglong2*>(&sA[r][k]); // LDS.128
            fma2(acc2[r], a2.x, wA);
            fma2(acc2[r], a2.y, wB);
        }
    }

    const float bb = b[tid];
    const float pa = *prelu_a;
    #pragma unroll
    for (int r = 0; r < GEMM_ROWS; r++) {
        int gr = r0 + r;
        if (gr < nrows) {
            float2 p = unpack2(acc2[r]);
            float z = p.x + p.y + bb;
            z = (z >= 0.f) ? z : pa * z;
            if (rowscale) z *= rowscale[gr];
            out[(size_t)gr * D + tid] = z;
        }
    }
}

// ---------------------------------------------------------------------------
// Launch sequence (graph-capturable, idempotent)
// ---------------------------------------------------------------------------
extern "C" void kernel_launch(void* const* d_in, const int* in_sizes, int n_in,
                              void* d_out, int out_size) {
    const float* x   = (const float*)d_in[0];
    const int*   src = (const int*)  d_in[1];
    const int*   dst = (const int*)  d_in[2];
    const float* W1  = (const float*)d_in[3];
    const float* b1  = (const float*)d_in[4];
    const float* W2  = (const float*)d_in[5];
    const float* b2  = (const float*)d_in[6];
    const float* pa  = (const float*)d_in[7];
    float*       out = (float*)d_out;

    float *deg_p, *xs_p, *agg_p, *z1_p;
    int *counts_p, *cursor_p, *rowptr_p, *bsums_p, *eidx_p;
    cudaGetSymbolAddress((void**)&deg_p,    g_deg);
    cudaGetSymbolAddress((void**)&counts_p, g_counts);
    cudaGetSymbolAddress((void**)&cursor_p, g_cursor);
    cudaGetSymbolAddress((void**)&rowptr_p, g_rowptr);
    cudaGetSymbolAddress((void**)&bsums_p,  g_bsums);
    cudaGetSymbolAddress((void**)&eidx_p,   g_eidx);
    cudaGetSymbolAddress((void**)&xs_p,     g_xs);
    cudaGetSymbolAddress((void**)&agg_p,    g_agg);
    cudaGetSymbolAddress((void**)&z1_p,     g_z1);

    const int TB = 256;
    const int node_grid = (N_NODES + TB - 1) / TB;
    const int edge_grid = (N_EDGES + TB - 1) / TB;

    // 1) degree + CSR build
    zero_small_kernel<<<node_grid, TB>>>(deg_p, counts_p, cursor_p);
    hist_kernel<<<edge_grid, TB>>>(src, dst, deg_p, counts_p);
    inv_kernel<<<node_grid, TB>>>(deg_p);
    scan_block_kernel<<<N_SCANBLK, SCAN_B>>>(counts_p, rowptr_p, bsums_p);
    scan_sums_kernel<<<1, 128>>>(bsums_p);
    scan_add_kernel<<<N_SCANBLK, SCAN_B>>>(rowptr_p, bsums_p);
    csr_fill_kernel<<<edge_grid, TB>>>(src, dst, rowptr_p, cursor_p, eidx_p);

    // 2) prescale layer-1 input by 1/outdeg
    const int n4 = (int)(ND / 4);
    prescale_kernel<<<(n4 + TB - 1) / TB, TB>>>((const float4*)x, deg_p, (float4*)xs_p);

    const int gather_grid = (N_NODES * 32 + TB - 1) / TB;   // warp per node
    const int gemm_grid   = (N_NODES + GEMM_ROWS - 1) / GEMM_ROWS;

    // 3) Layer 1: gather(xs) -> gemm (epilogue scales by inv for layer-2 gather)
    gather_kernel<<<gather_grid, TB>>>(xs_p, rowptr_p, eidx_p, agg_p);
    gemm_prelu_kernel<<<gemm_grid, 128>>>(agg_p, W1, b1, pa, deg_p, z1_p, N_NODES);

    // 4) Layer 2: gather(z1_scaled) -> gemm (no epilogue scale)
    gather_kernel<<<gather_grid, TB>>>(z1_p, rowptr_p, eidx_p, agg_p);
    gemm_prelu_kernel<<<gemm_grid, 128>>>(agg_p, W2, b2, pa, (const float*)nullptr, out, N_NODES);
}